// round 7
// baseline (speedup 1.0000x reference)
#include <cuda_runtime.h>
#include <cuda_fp16.h>
#include <mma.h>
#include <cstdint>
using namespace nvcuda;

#define SCALE_F 0.17677669529663687f   // 32^-0.5

// prepacked weights (device scratch)
__device__ __half g_w1[8 * 96 * 256];    // per-head fused [q(scaled)|k|v][256]
__device__ __half g_w4p[8 * 256 * 32];   // wp repacked: [h][out_n][k]
__device__ float  g_bf[8 * 64 * 64];     // btab[rel_idx] per head
__device__ float  g_b1v[8 * 96];         // fused bias (q part scaled)

// smem layout (pitches in elements)
#define XP   264   // X [64][264] half  (epilogue: f32 [32][260] overlay)
#define QKP  104   // qkv head [64][104] half ; oh overlay pitch 40
#define SPP  68    // fp32 scratch [64][68]   ; ph overlay pitch 72 half
#define PHP  72
#define WSP  72    // GEMM1 weight chunk [96][72] half x2
#define WPP  40    // wp head buffer [256][40] half
#define OHP  40

#define SM_X   0u
#define SM_QK  33792u
#define SM_SP  47104u
#define SM_WS  64512u     // 2 x 96*72*2 = 27648
#define SM_WP  92160u     // 256*40*2 = 20480
#define SMEM_BYTES 112640u

typedef wmma::fragment<wmma::matrix_a, 16, 16, 16, __half, wmma::row_major> FragA;
typedef wmma::fragment<wmma::matrix_b, 16, 16, 16, __half, wmma::col_major> FragBc;
typedef wmma::fragment<wmma::matrix_b, 16, 16, 16, __half, wmma::row_major> FragBr;
typedef wmma::fragment<wmma::accumulator, 16, 16, 16, float> FragC;

__device__ __forceinline__ uint32_t smem_u32(const void* p) {
    uint32_t a;
    asm("{ .reg .u64 t; cvta.to.shared.u64 t, %1; cvt.u32.u64 %0, t; }" : "=r"(a) : "l"(p));
    return a;
}
__device__ __forceinline__ void cp16(uint32_t dst, const void* src) {
    asm volatile("cp.async.ca.shared.global [%0], [%1], 16;" :: "r"(dst), "l"(src));
}
#define CP_COMMIT() asm volatile("cp.async.commit_group;" ::: "memory")
#define CP_WAIT0()  asm volatile("cp.async.wait_group 0;" ::: "memory")

// ---------------- prep: pack weights fp16 / pre-gather bias ----------------
__global__ void prep_kernel(const float* __restrict__ wq,  const float* __restrict__ bq,
                            const float* __restrict__ wkv, const float* __restrict__ bkv,
                            const float* __restrict__ wp,
                            const float* __restrict__ btab, const int* __restrict__ ridx)
{
    int idx = blockIdx.x * 256 + threadIdx.x;
    if (idx < 196608) {                       // g_w1
        int h = idx / 24576, r = idx % 24576;
        int f = r >> 8, c = r & 255;
        float v;
        if (f < 32)      v = wq[(size_t)(h * 32 + f) * 256 + c] * SCALE_F;
        else if (f < 64) v = wkv[(size_t)(h * 32 + f - 32) * 256 + c];
        else             v = wkv[(size_t)(256 + h * 32 + f - 64) * 256 + c];
        g_w1[idx] = __float2half_rn(v);
    } else if (idx < 262144) {                // g_w4p [h][n][k] = wp[n][32h+k]
        int i = idx - 196608;
        int n = i >> 8, c = i & 255;
        int h = c >> 5, k = c & 31;
        g_w4p[(h * 256 + n) * 32 + k] = __float2half_rn(wp[n * 256 + c]);
    } else if (idx < 294912) {                // g_bf
        int i = idx - 262144;
        int h = i >> 12, nm = i & 4095;
        g_bf[i] = btab[ridx[nm] * 8 + h];
    } else if (idx < 295680) {                // g_b1v
        int i = idx - 294912;
        int h = i / 96, f = i % 96;
        float v;
        if (f < 32)      v = bq[h * 32 + f] * SCALE_F;
        else if (f < 64) v = bkv[h * 32 + f - 32];
        else             v = bkv[256 + h * 32 + f - 64];
        g_b1v[i] = v;
    }
}

// ---------------- main kernel ----------------
__global__ __launch_bounds__(256, 2)
void winattn_h16c(const float* __restrict__ x, const float* __restrict__ mask,
                  const float* __restrict__ bp, float* __restrict__ out)
{
    extern __shared__ char smem[];
    __half* xs  = (__half*)(smem + SM_X);
    float*  xsf = (float*)(smem + SM_X);     // epilogue overlay [32][260]
    __half* qk  = (__half*)(smem + SM_QK);
    __half* oh  = (__half*)(smem + SM_QK);   // O_h half overlay [64][40]
    float*  sp  = (float*)(smem + SM_SP);
    __half* ph  = (__half*)(smem + SM_SP);   // P overlay, pitch 72
    __half* ws0 = (__half*)(smem + SM_WS);
    __half* ws1 = ws0 + 96 * WSP;
    __half* wpb = (__half*)(smem + SM_WP);

    const uint32_t wsa0 = smem_u32(ws0);
    const uint32_t wsa1 = smem_u32(ws1);
    const uint32_t wpa  = smem_u32(wpb);
    const int tid = threadIdx.x;
    const int w   = tid >> 5;
    const int b   = blockIdx.x;

    // stage X as fp16
    const float4* xg = (const float4*)(x + (size_t)b * 16384);
    #pragma unroll
    for (int i = 0; i < 16; i++) {
        int idx = tid + 256 * i;
        int t = idx >> 6, c4 = idx & 63;
        float4 v = xg[idx];
        __half2* d = (__half2*)(xs + t * XP + c4 * 4);
        d[0] = __floats2half2_rn(v.x, v.y);
        d[1] = __floats2half2_rn(v.z, v.w);
    }

    const int mi  = w >> 1;   // GEMM1/2 row tile
    const int nh  = w & 1;    // GEMM1/2 col half
    const int miq = w >> 2;   // GEMM4 row pair
    const int nc  = w & 3;    // GEMM4 col quad

    // persistent out accumulators: warp owns rows [miq*32, +32), cols [nc*64, +64)
    FragC acc4[2][4];
    #pragma unroll
    for (int r = 0; r < 2; r++)
        #pragma unroll
        for (int j = 0; j < 4; j++) wmma::fill_fragment(acc4[r][j], 0.f);

    for (int h = 0; h < 8; h++) {
        const __half* w1h = g_w1 + h * 24576;
        // ---- GEMM1: QKV_h[64,96] = X @ W1_h^T ; K chunks of 64, dbuf ----
        FragC acc[3];
        #pragma unroll
        for (int j = 0; j < 3; j++) wmma::fill_fragment(acc[j], 0.f);

        {   // prologue chunk 0 -> ws0 (96 rows x 64 cols = 768 x16B)
            #pragma unroll
            for (int i = 0; i < 3; i++) {
                int idx = tid + 256 * i;
                int f = idx >> 3, p = idx & 7;
                cp16(wsa0 + f * 144 + p * 16, w1h + f * 256 + p * 8);
            }
            CP_COMMIT();
        }
        for (int kc = 0; kc < 4; kc++) {
            CP_WAIT0();
            __syncthreads();
            if (kc < 3) {
                uint32_t dst = (kc & 1) ? wsa0 : wsa1;
                #pragma unroll
                for (int i = 0; i < 3; i++) {
                    int idx = tid + 256 * i;
                    int f = idx >> 3, p = idx & 7;
                    cp16(dst + f * 144 + p * 16, w1h + f * 256 + (kc + 1) * 64 + p * 8);
                }
                CP_COMMIT();
            }
            __half* wb = (kc & 1) ? ws1 : ws0;
            #pragma unroll
            for (int k8 = 0; k8 < 4; k8++) {
                FragA fa;
                wmma::load_matrix_sync(fa, xs + mi * 16 * XP + kc * 64 + k8 * 16, XP);
                #pragma unroll
                for (int j = 0; j < 3; j++) {
                    FragBc fb;
                    wmma::load_matrix_sync(fb, wb + (nh * 3 + j) * 16 * WSP + k8 * 16, WSP);
                    wmma::mma_sync(acc[j], fa, fb, acc[j]);
                }
            }
        }
        // prefetch wp_h for fused GEMM4 (consumed after GEMM3)
        {
            const __half* w4h = g_w4p + h * 8192;
            #pragma unroll
            for (int i = 0; i < 4; i++) {
                int idx = tid + 256 * i;
                int n = idx >> 2, p = idx & 3;
                cp16(wpa + n * 80 + p * 16, w4h + n * 32 + p * 8);
            }
            CP_COMMIT();
        }

        // ---- bias fixup -> qk half (2 batches of 48 cols) ----
        #pragma unroll
        for (int bb = 0; bb < 2; bb++) {
            if (nh == bb) {
                #pragma unroll
                for (int j = 0; j < 3; j++)
                    wmma::store_matrix_sync(sp + mi * 16 * SPP + j * 16, acc[j], SPP, wmma::mem_row_major);
            }
            __syncthreads();
            #pragma unroll
            for (int i = 0; i < 12; i++) {
                int idx = tid + 256 * i;
                int t = idx / 48, c = idx % 48;
                int col = bb * 48 + c;
                qk[t * QKP + col] = __float2half_rn(sp[t * SPP + c] + g_b1v[h * 96 + col]);
            }
            __syncthreads();
        }

        // ---- GEMM2: S = Q K^T -> sp ----
        {
            FragC c2[2];
            #pragma unroll
            for (int j = 0; j < 2; j++) wmma::fill_fragment(c2[j], 0.f);
            #pragma unroll
            for (int k8 = 0; k8 < 2; k8++) {
                FragA fa;
                wmma::load_matrix_sync(fa, qk + mi * 16 * QKP + k8 * 16, QKP);
                #pragma unroll
                for (int j = 0; j < 2; j++) {
                    FragBc fb;
                    wmma::load_matrix_sync(fb, qk + (nh * 2 + j) * 16 * QKP + 32 + k8 * 16, QKP);
                    wmma::mma_sync(c2[j], fa, fb, c2[j]);
                }
            }
            #pragma unroll
            for (int j = 0; j < 2; j++)
                wmma::store_matrix_sync(sp + mi * 16 * SPP + (nh * 2 + j) * 16, c2[j], SPP, wmma::mem_row_major);
        }
        __syncthreads();

        // ---- softmax: 4 threads/row -> ph (half, pitch 72) ----
        {
            int n = tid >> 2, q = tid & 3;
            const float* srow = sp + n * SPP + q * 16;
            const float* brow = g_bf + (h * 64 + n) * 64 + q * 16;
            const float* mrow = mask + (size_t)(b & 4095) * 4096 + n * 64 + q * 16;
            float vb[16];
            float mx = -1e30f;
            #pragma unroll
            for (int m = 0; m < 16; m++) {
                float v = srow[m] + brow[m] + __ldg(mrow + m);
                vb[m] = v;
                mx = fmaxf(mx, v);
            }
            mx = fmaxf(mx, __shfl_xor_sync(0xffffffffu, mx, 1));
            mx = fmaxf(mx, __shfl_xor_sync(0xffffffffu, mx, 2));
            float s = 0.f;
            #pragma unroll
            for (int m = 0; m < 16; m++) {
                float p = __expf(vb[m] - mx);
                vb[m] = p;
                s += p;
            }
            s += __shfl_xor_sync(0xffffffffu, s, 1);
            s += __shfl_xor_sync(0xffffffffu, s, 2);
            float inv = 1.f / s;
            __syncthreads();               // sp reads done before ph overlay write
            #pragma unroll
            for (int m = 0; m < 16; m++)
                ph[n * PHP + q * 16 + m] = __float2half_rn(vb[m] * inv);
        }
        __syncthreads();

        // ---- GEMM3: O_h = P @ V ----
        {
            int m3 = w >> 1, n3 = w & 1;
            FragC c3; wmma::fill_fragment(c3, 0.f);
            #pragma unroll
            for (int k8 = 0; k8 < 4; k8++) {
                FragA fa; FragBr fb;
                wmma::load_matrix_sync(fa, ph + m3 * 16 * PHP + k8 * 16, PHP);
                wmma::load_matrix_sync(fb, qk + (k8 * 16) * QKP + 64 + n3 * 16, QKP);
                wmma::mma_sync(c3, fa, fb, c3);
            }
            __syncthreads();               // ph/qk reads done
            wmma::store_matrix_sync(sp + m3 * 16 * SPP + n3 * 16, c3, SPP, wmma::mem_row_major);
        }
        __syncthreads();
        // convert O_h -> oh half (overlay on qk region)
        #pragma unroll
        for (int i = 0; i < 8; i++) {
            int idx = tid + 256 * i;
            int t = idx >> 5, c = idx & 31;
            oh[t * OHP + c] = __float2half_rn(sp[t * SPP + c]);
        }
        __syncthreads();

        // ---- fused GEMM4: acc4 += O_h @ wp_h^T  (K=32) ----
        CP_WAIT0();                        // wp_h staged
        __syncthreads();
        #pragma unroll
        for (int k8 = 0; k8 < 2; k8++) {
            FragA fa[2];
            #pragma unroll
            for (int r = 0; r < 2; r++)
                wmma::load_matrix_sync(fa[r], oh + (2 * miq + r) * 16 * OHP + k8 * 16, OHP);
            #pragma unroll
            for (int j = 0; j < 4; j++) {
                FragBc fb;
                wmma::load_matrix_sync(fb, wpb + (4 * nc + j) * 16 * WPP + k8 * 16, WPP);
                #pragma unroll
                for (int r = 0; r < 2; r++)
                    wmma::mma_sync(acc4[r][j], fa[r], fb, acc4[r][j]);
            }
        }
        // no sync needed: next-phase qk/oh writes are behind GEMM1's barriers
    }

    // ---------- epilogue: acc4 -> xsf (f32, pitch 260) -> +bp -> out ----------
    __syncthreads();
    #pragma unroll
    for (int p = 0; p < 2; p++) {
        if (miq == p) {
            #pragma unroll
            for (int r = 0; r < 2; r++)
                #pragma unroll
                for (int j = 0; j < 4; j++)
                    wmma::store_matrix_sync(xsf + (r * 16) * 260 + nc * 64 + j * 16,
                                            acc4[r][j], 260, wmma::mem_row_major);
        }
        __syncthreads();
        float* og = out + (size_t)b * 16384 + (size_t)(32 * p) * 256;
        #pragma unroll
        for (int i = 0; i < 8; i++) {
            int idx = tid + 256 * i;
            int t = idx >> 6, c4 = idx & 63;
            const float* s = xsf + t * 260 + c4 * 4;
            float4 o;
            o.x = s[0] + __ldg(bp + c4 * 4 + 0);
            o.y = s[1] + __ldg(bp + c4 * 4 + 1);
            o.z = s[2] + __ldg(bp + c4 * 4 + 2);
            o.w = s[3] + __ldg(bp + c4 * 4 + 3);
            *(float4*)(og + t * 256 + c4 * 4) = o;
        }
        __syncthreads();
    }
}

extern "C" void kernel_launch(void* const* d_in, const int* in_sizes, int n_in,
                              void* d_out, int out_size)
{
    const float* x    = (const float*)d_in[0];
    const float* mask = (const float*)d_in[1];
    const float* wq   = (const float*)d_in[2];
    const float* bq   = (const float*)d_in[3];
    const float* wkv  = (const float*)d_in[4];
    const float* bkv  = (const float*)d_in[5];
    const float* wp   = (const float*)d_in[6];
    const float* bp   = (const float*)d_in[7];
    const float* bt   = (const float*)d_in[8];
    const int*   ri   = (const int*)d_in[9];
    float* out = (float*)d_out;

    prep_kernel<<<1155, 256>>>(wq, bq, wkv, bkv, wp, bt, ri);
    cudaFuncSetAttribute(winattn_h16c,
                         cudaFuncAttributeMaxDynamicSharedMemorySize, SMEM_BYTES);
    winattn_h16c<<<8192, 256, SMEM_BYTES>>>(x, mask, bp, out);
}